// round 14
// baseline (speedup 1.0000x reference)
#include <cuda_runtime.h>
#include <cuda_bf16.h>

// PathSampling, warp-per-2-nodes (ILP x2) + cache-policy split.
// Two independent node streams per warp -> ~16 outstanding gathers between
// dependency joins, filling the L1tex pipe that R11 left at 70%.

__global__ __launch_bounds__(256) void path_sampling_kernel(
    const int*   __restrict__ paths,      // [n_node, 32, 8]
    const int*   __restrict__ edge_ids,   // [n_node, 32, 7]
    const int*   __restrict__ rand_lens,  // [n_node, 32]
    const float* __restrict__ centrality, // [n_graph]
    float*       __restrict__ out_paths,  // [n_node, 8, 8] float32
    float*       __restrict__ out_edges,  // [n_node, 8, 7] float32
    int n_node)
{
    const int warp_id = (blockIdx.x * blockDim.x + threadIdx.x) >> 5;
    const int lane    = threadIdx.x & 31;

    const int nodeA = warp_id * 2;
    const int nodeB = nodeA + 1;
    if (nodeA >= n_node) return;
    const bool hasB = (nodeB < n_node);

    // ---- streaming loads for both nodes (evict-first) ----
    const int4* prowA = reinterpret_cast<const int4*>(paths + ((long long)nodeA * 32 + lane) * 8);
    const int4* prowB = reinterpret_cast<const int4*>(paths + ((long long)nodeB * 32 + lane) * 8);
    int4 a0 = __ldcs(prowA + 0);
    int4 a1 = __ldcs(prowA + 1);
    int4 b0, b1;
    int lenB = 0;
    if (hasB) { b0 = __ldcs(prowB + 0); b1 = __ldcs(prowB + 1); lenB = __ldcs(rand_lens + (long long)nodeB * 32 + lane); }
    else      { b0 = make_int4(0,0,0,0); b1 = b0; }
    const int lenA = __ldcs(rand_lens + (long long)nodeA * 32 + lane);

    int mA[8] = {a0.x, a0.y, a0.z, a0.w, a1.x, a1.y, a1.z, a1.w};
    int mB[8] = {b0.x, b0.y, b0.z, b0.w, b1.x, b1.y, b1.z, b1.w};

    // ---- mask + score, both streams interleaved ----
    float sA = 0.0f, sB = 0.0f;
#pragma unroll
    for (int j = 0; j < 8; j++) {
        if (j > lenA) mA[j] = -1; else sA += __ldg(centrality + mA[j]);
        if (hasB) { if (j > lenB) mB[j] = -1; else sB += __ldg(centrality + mB[j]); }
    }

    // ---- stable ranks (two independent shfl chains) ----
    int rkA = 0, rkB = 0;
#pragma unroll
    for (int j = 0; j < 32; j++) {
        float xa = __shfl_sync(0xffffffffu, sA, j);
        float xb = __shfl_sync(0xffffffffu, sB, j);
        rkA += (xa > sA) || (xa == sA && j < lane);
        rkB += (xb > sB) || (xb == sB && j < lane);
    }

    // ---- slot -> source lane maps ----
    int srcA = 0, srcB = 0;
#pragma unroll
    for (int r = 0; r < 8; r++) {
        unsigned ma = __ballot_sync(0xffffffffu, rkA == r);
        unsigned mb = __ballot_sync(0xffffffffu, rkB == r);
        if (lane == r) { srcA = __ffs(ma) - 1; srcB = __ffs(mb) - 1; }
    }

    // ---- path-row writes (evict-first) ----
    if (rkA < 8) {
        float4* op = reinterpret_cast<float4*>(out_paths + ((long long)nodeA * 8 + rkA) * 8);
        __stcs(op + 0, make_float4((float)mA[0], (float)mA[1], (float)mA[2], (float)mA[3]));
        __stcs(op + 1, make_float4((float)mA[4], (float)mA[5], (float)mA[6], (float)mA[7]));
    }
    if (hasB && rkB < 8) {
        float4* op = reinterpret_cast<float4*>(out_paths + ((long long)nodeB * 8 + rkB) * 8);
        __stcs(op + 0, make_float4((float)mB[0], (float)mB[1], (float)mB[2], (float)mB[3]));
        __stcs(op + 1, make_float4((float)mB[4], (float)mB[5], (float)mB[6], (float)mB[7]));
    }

    // ---- warp-cooperative edge copies ----
    {
        const int* eb = edge_ids + (long long)nodeA * (32 * 7);
        float*     ob = out_edges + (long long)nodeA * 56;
#pragma unroll
        for (int pass = 0; pass < 2; pass++) {
            int e = lane + pass * 32;
            int s = e / 7;
            int j = e - s * 7;
            int src = __shfl_sync(0xffffffffu, srcA, s & 7);
            if (e < 56) __stcs(ob + e, (float)__ldcs(eb + src * 7 + j));
        }
    }
    if (hasB) {
        const int* eb = edge_ids + (long long)nodeB * (32 * 7);
        float*     ob = out_edges + (long long)nodeB * 56;
#pragma unroll
        for (int pass = 0; pass < 2; pass++) {
            int e = lane + pass * 32;
            int s = e / 7;
            int j = e - s * 7;
            int src = __shfl_sync(0xffffffffu, srcB, s & 7);
            if (e < 56) __stcs(ob + e, (float)__ldcs(eb + src * 7 + j));
        }
    }
}

extern "C" void kernel_launch(void* const* d_in, const int* in_sizes, int n_in,
                              void* d_out, int out_size) {
    // Bind inputs by DESCENDING element count (all distinct, order-agnostic):
    //   paths 25.6M > edge_ids 22.4M > rand_lens 3.2M > centrality 100K;
    //   size-1 k_path scalar ignored (constant 8).
    int idx[8];
    int m = 0;
    for (int i = 0; i < n_in && m < 8; i++) {
        if (in_sizes[i] > 1) idx[m++] = i;
    }
    for (int a = 1; a < m; a++) {
        int v = idx[a];
        int b = a - 1;
        while (b >= 0 && in_sizes[idx[b]] < in_sizes[v]) { idx[b + 1] = idx[b]; b--; }
        idx[b + 1] = v;
    }

    const int*   paths      = (const int*)  d_in[idx[0]];
    const int*   edge_ids   = (const int*)  d_in[idx[1]];
    const int*   rand_lens  = (const int*)  d_in[idx[2]];
    const float* centrality = (const float*)d_in[idx[3]];

    const int n_node = in_sizes[idx[0]] / (32 * 8);

    float* out_paths = (float*)d_out;                       // [n_node, 8, 8]
    float* out_edges = out_paths + (long long)n_node * 64;  // [n_node, 8, 7]

    const int threads = 256;                  // 8 warps -> 16 nodes per block
    const int nodes_per_block = 16;
    const int blocks = (n_node + nodes_per_block - 1) / nodes_per_block;
    path_sampling_kernel<<<blocks, threads>>>(paths, edge_ids, rand_lens,
                                              centrality, out_paths, out_edges,
                                              n_node);
}

// round 15
// speedup vs baseline: 1.1666x; 1.1666x over previous
#include <cuda_runtime.h>
#include <cuda_bf16.h>

// PathSampling, warp-per-node + cache-policy split (streaming = evict-first).
// R15: 128-thread blocks — finer occupancy granularity (4-warp allocation,
// 25000 blocks) to push warp residency toward the 64-slot limit and fill the
// L1tex pipe (R11: occ 89%, L1 70.6%). Logic identical to R11 (best: 73.8us).

__global__ __launch_bounds__(128) void path_sampling_kernel(
    const int*   __restrict__ paths,      // [n_node, 32, 8]
    const int*   __restrict__ edge_ids,   // [n_node, 32, 7]
    const int*   __restrict__ rand_lens,  // [n_node, 32]
    const float* __restrict__ centrality, // [n_graph]
    float*       __restrict__ out_paths,  // [n_node, 8, 8] float32
    float*       __restrict__ out_edges,  // [n_node, 8, 7] float32
    int n_node)
{
    const int warp_id = (blockIdx.x * blockDim.x + threadIdx.x) >> 5;
    const int lane    = threadIdx.x & 31;
    if (warp_id >= n_node) return;
    const long long node = warp_id;

    // ---- streaming loads: evict-first so they don't churn L1D ----
    const int4* prow = reinterpret_cast<const int4*>(paths + (node * 32 + lane) * 8);
    int4 p0 = __ldcs(prow + 0);
    int4 p1 = __ldcs(prow + 1);
    const int len = __ldcs(rand_lens + node * 32 + lane);

    int mp[8] = {p0.x, p0.y, p0.z, p0.w, p1.x, p1.y, p1.z, p1.w};

    // ---- mask (pos > len -> -1) + score; gathers keep normal caching ----
    float score = 0.0f;
#pragma unroll
    for (int j = 0; j < 8; j++) {
        if (j > len) {
            mp[j] = -1;
        } else {
            score += __ldg(centrality + mp[j]);
        }
    }

    // ---- stable rank among 32 lanes: higher score first, tie -> lower lane ----
    int rank = 0;
#pragma unroll
    for (int j = 0; j < 32; j++) {
        float sj = __shfl_sync(0xffffffffu, score, j);
        rank += (sj > score) || (sj == score && j < lane);
    }

    // ---- slot -> source lane map (lane r holds src lane of rank r) ----
    int my_src = 0;
#pragma unroll
    for (int r = 0; r < 8; r++) {
        unsigned mr = __ballot_sync(0xffffffffu, rank == r);
        if (lane == r) my_src = __ffs(mr) - 1;
    }

    // ---- selected lanes write their path row (float32, evict-first) ----
    if (rank < 8) {
        float4* op = reinterpret_cast<float4*>(out_paths + (node * 8 + rank) * 8);
        __stcs(op + 0, make_float4((float)mp[0], (float)mp[1], (float)mp[2], (float)mp[3]));
        __stcs(op + 1, make_float4((float)mp[4], (float)mp[5], (float)mp[6], (float)mp[7]));
    }

    // ---- warp-cooperative edge copy: 56 contiguous floats/node ----
    const int* ebase = edge_ids + node * (32 * 7);
    float*     obase = out_edges + node * 56;
#pragma unroll
    for (int pass = 0; pass < 2; pass++) {
        int e = lane + pass * 32;
        int s = e / 7;
        int j = e - s * 7;
        int src = __shfl_sync(0xffffffffu, my_src, s & 7);
        if (e < 56) {
            __stcs(obase + e, (float)__ldcs(ebase + src * 7 + j));
        }
    }
}

extern "C" void kernel_launch(void* const* d_in, const int* in_sizes, int n_in,
                              void* d_out, int out_size) {
    // Bind inputs by DESCENDING element count (all distinct, order-agnostic):
    //   paths 25.6M > edge_ids 22.4M > rand_lens 3.2M > centrality 100K;
    //   size-1 k_path scalar ignored (constant 8).
    int idx[8];
    int m = 0;
    for (int i = 0; i < n_in && m < 8; i++) {
        if (in_sizes[i] > 1) idx[m++] = i;
    }
    for (int a = 1; a < m; a++) {
        int v = idx[a];
        int b = a - 1;
        while (b >= 0 && in_sizes[idx[b]] < in_sizes[v]) { idx[b + 1] = idx[b]; b--; }
        idx[b + 1] = v;
    }

    const int*   paths      = (const int*)  d_in[idx[0]];
    const int*   edge_ids   = (const int*)  d_in[idx[1]];
    const int*   rand_lens  = (const int*)  d_in[idx[2]];
    const float* centrality = (const float*)d_in[idx[3]];

    const int n_node = in_sizes[idx[0]] / (32 * 8);

    float* out_paths = (float*)d_out;                       // [n_node, 8, 8]
    float* out_edges = out_paths + (long long)n_node * 64;  // [n_node, 8, 7]

    const int threads = 128;                  // 4 warps -> 4 nodes per block
    const int blocks  = (n_node + 3) / 4;
    path_sampling_kernel<<<blocks, threads>>>(paths, edge_ids, rand_lens,
                                              centrality, out_paths, out_edges,
                                              n_node);
}

// round 16
// speedup vs baseline: 1.2026x; 1.0309x over previous
#include <cuda_runtime.h>
#include <cuda_bf16.h>

// PathSampling, warp-per-node, 128-thr blocks, cache-policy split.
// R16: gather MLP fix — two 4-load batches (loads issued before their adds,
// adds kept in R11's exact sequential order for bit-identical scores).
// __launch_bounds__(128,16) pins regs<=32 so 64-warp occupancy is preserved.

__global__ __launch_bounds__(128, 16) void path_sampling_kernel(
    const int*   __restrict__ paths,      // [n_node, 32, 8]
    const int*   __restrict__ edge_ids,   // [n_node, 32, 7]
    const int*   __restrict__ rand_lens,  // [n_node, 32]
    const float* __restrict__ centrality, // [n_graph]
    float*       __restrict__ out_paths,  // [n_node, 8, 8] float32
    float*       __restrict__ out_edges,  // [n_node, 8, 7] float32
    int n_node)
{
    const int warp_id = (blockIdx.x * blockDim.x + threadIdx.x) >> 5;
    const int lane    = threadIdx.x & 31;
    if (warp_id >= n_node) return;
    const long long node = warp_id;

    // ---- streaming loads: evict-first so they don't churn L1D ----
    const int4* prow = reinterpret_cast<const int4*>(paths + (node * 32 + lane) * 8);
    int4 p0 = __ldcs(prow + 0);
    int4 p1 = __ldcs(prow + 1);
    const int len = __ldcs(rand_lens + node * 32 + lane);

    int mp[8] = {p0.x, p0.y, p0.z, p0.w, p1.x, p1.y, p1.z, p1.w};

    // ---- mask (pos > len -> -1) ----
#pragma unroll
    for (int j = 0; j < 8; j++)
        if (j > len) mp[j] = -1;

    // ---- score: two 4-wide load batches, adds in sequential (R11) order ----
    float score = 0.0f;
    {
        float v0 = 0.0f, v1 = 0.0f, v2 = 0.0f, v3 = 0.0f;
        if (0 <= len) v0 = __ldg(centrality + mp[0]);
        if (1 <= len) v1 = __ldg(centrality + mp[1]);
        if (2 <= len) v2 = __ldg(centrality + mp[2]);
        if (3 <= len) v3 = __ldg(centrality + mp[3]);
        score += v0; score += v1; score += v2; score += v3;
    }
    {
        float v0 = 0.0f, v1 = 0.0f, v2 = 0.0f, v3 = 0.0f;
        if (4 <= len) v0 = __ldg(centrality + mp[4]);
        if (5 <= len) v1 = __ldg(centrality + mp[5]);
        if (6 <= len) v2 = __ldg(centrality + mp[6]);
        if (7 <= len) v3 = __ldg(centrality + mp[7]);
        score += v0; score += v1; score += v2; score += v3;
    }

    // ---- stable rank among 32 lanes: higher score first, tie -> lower lane ----
    int rank = 0;
#pragma unroll
    for (int j = 0; j < 32; j++) {
        float sj = __shfl_sync(0xffffffffu, score, j);
        rank += (sj > score) || (sj == score && j < lane);
    }

    // ---- slot -> source lane map (lane r holds src lane of rank r) ----
    int my_src = 0;
#pragma unroll
    for (int r = 0; r < 8; r++) {
        unsigned mr = __ballot_sync(0xffffffffu, rank == r);
        if (lane == r) my_src = __ffs(mr) - 1;
    }

    // ---- selected lanes write their path row (float32, evict-first) ----
    if (rank < 8) {
        float4* op = reinterpret_cast<float4*>(out_paths + (node * 8 + rank) * 8);
        __stcs(op + 0, make_float4((float)mp[0], (float)mp[1], (float)mp[2], (float)mp[3]));
        __stcs(op + 1, make_float4((float)mp[4], (float)mp[5], (float)mp[6], (float)mp[7]));
    }

    // ---- warp-cooperative edge copy: 56 contiguous floats/node ----
    const int* ebase = edge_ids + node * (32 * 7);
    float*     obase = out_edges + node * 56;
#pragma unroll
    for (int pass = 0; pass < 2; pass++) {
        int e = lane + pass * 32;
        int s = e / 7;
        int j = e - s * 7;
        int src = __shfl_sync(0xffffffffu, my_src, s & 7);
        if (e < 56) {
            __stcs(obase + e, (float)__ldcs(ebase + src * 7 + j));
        }
    }
}

extern "C" void kernel_launch(void* const* d_in, const int* in_sizes, int n_in,
                              void* d_out, int out_size) {
    // Bind inputs by DESCENDING element count (all distinct, order-agnostic):
    //   paths 25.6M > edge_ids 22.4M > rand_lens 3.2M > centrality 100K;
    //   size-1 k_path scalar ignored (constant 8).
    int idx[8];
    int m = 0;
    for (int i = 0; i < n_in && m < 8; i++) {
        if (in_sizes[i] > 1) idx[m++] = i;
    }
    for (int a = 1; a < m; a++) {
        int v = idx[a];
        int b = a - 1;
        while (b >= 0 && in_sizes[idx[b]] < in_sizes[v]) { idx[b + 1] = idx[b]; b--; }
        idx[b + 1] = v;
    }

    const int*   paths      = (const int*)  d_in[idx[0]];
    const int*   edge_ids   = (const int*)  d_in[idx[1]];
    const int*   rand_lens  = (const int*)  d_in[idx[2]];
    const float* centrality = (const float*)d_in[idx[3]];

    const int n_node = in_sizes[idx[0]] / (32 * 8);

    float* out_paths = (float*)d_out;                       // [n_node, 8, 8]
    float* out_edges = out_paths + (long long)n_node * 64;  // [n_node, 8, 7]

    const int threads = 128;                  // 4 warps -> 4 nodes per block
    const int blocks  = (n_node + 3) / 4;
    path_sampling_kernel<<<blocks, threads>>>(paths, edge_ids, rand_lens,
                                              centrality, out_paths, out_edges,
                                              n_node);
}

// round 17
// speedup vs baseline: 1.2228x; 1.0168x over previous
#include <cuda_runtime.h>
#include <cuda_bf16.h>

// PathSampling, warp-per-node, 128-thr blocks, cache-policy split.
// R17: full 8-wide gather batch — all 8 centrality loads issued before any
// adds (MLP 8 vs R16's 4); adds remain strictly sequential so scores are
// bit-identical to all passing rounds. launch_bounds(128,16) pins regs<=32.

__global__ __launch_bounds__(128, 16) void path_sampling_kernel(
    const int*   __restrict__ paths,      // [n_node, 32, 8]
    const int*   __restrict__ edge_ids,   // [n_node, 32, 7]
    const int*   __restrict__ rand_lens,  // [n_node, 32]
    const float* __restrict__ centrality, // [n_graph]
    float*       __restrict__ out_paths,  // [n_node, 8, 8] float32
    float*       __restrict__ out_edges,  // [n_node, 8, 7] float32
    int n_node)
{
    const int warp_id = (blockIdx.x * blockDim.x + threadIdx.x) >> 5;
    const int lane    = threadIdx.x & 31;
    if (warp_id >= n_node) return;
    const long long node = warp_id;

    // ---- streaming loads: evict-first so they don't churn L1D ----
    const int4* prow = reinterpret_cast<const int4*>(paths + (node * 32 + lane) * 8);
    int4 p0 = __ldcs(prow + 0);
    int4 p1 = __ldcs(prow + 1);
    const int len = __ldcs(rand_lens + node * 32 + lane);

    int mp[8] = {p0.x, p0.y, p0.z, p0.w, p1.x, p1.y, p1.z, p1.w};

    // ---- mask (pos > len -> -1) ----
#pragma unroll
    for (int j = 0; j < 8; j++)
        if (j > len) mp[j] = -1;

    // ---- score: single 8-wide load batch, adds sequential (bit-identical) ----
    float v[8];
#pragma unroll
    for (int j = 0; j < 8; j++)
        v[j] = (j <= len) ? __ldg(centrality + mp[j]) : 0.0f;

    float score = 0.0f;
#pragma unroll
    for (int j = 0; j < 8; j++)
        score += v[j];

    // ---- stable rank among 32 lanes: higher score first, tie -> lower lane ----
    int rank = 0;
#pragma unroll
    for (int j = 0; j < 32; j++) {
        float sj = __shfl_sync(0xffffffffu, score, j);
        rank += (sj > score) || (sj == score && j < lane);
    }

    // ---- slot -> source lane map (lane r holds src lane of rank r) ----
    int my_src = 0;
#pragma unroll
    for (int r = 0; r < 8; r++) {
        unsigned mr = __ballot_sync(0xffffffffu, rank == r);
        if (lane == r) my_src = __ffs(mr) - 1;
    }

    // ---- selected lanes write their path row (float32, evict-first) ----
    if (rank < 8) {
        float4* op = reinterpret_cast<float4*>(out_paths + (node * 8 + rank) * 8);
        __stcs(op + 0, make_float4((float)mp[0], (float)mp[1], (float)mp[2], (float)mp[3]));
        __stcs(op + 1, make_float4((float)mp[4], (float)mp[5], (float)mp[6], (float)mp[7]));
    }

    // ---- warp-cooperative edge copy: 56 contiguous floats/node ----
    const int* ebase = edge_ids + node * (32 * 7);
    float*     obase = out_edges + node * 56;
#pragma unroll
    for (int pass = 0; pass < 2; pass++) {
        int e = lane + pass * 32;
        int s = e / 7;
        int j = e - s * 7;
        int src = __shfl_sync(0xffffffffu, my_src, s & 7);
        if (e < 56) {
            __stcs(obase + e, (float)__ldcs(ebase + src * 7 + j));
        }
    }
}

extern "C" void kernel_launch(void* const* d_in, const int* in_sizes, int n_in,
                              void* d_out, int out_size) {
    // Bind inputs by DESCENDING element count (all distinct, order-agnostic):
    //   paths 25.6M > edge_ids 22.4M > rand_lens 3.2M > centrality 100K;
    //   size-1 k_path scalar ignored (constant 8).
    int idx[8];
    int m = 0;
    for (int i = 0; i < n_in && m < 8; i++) {
        if (in_sizes[i] > 1) idx[m++] = i;
    }
    for (int a = 1; a < m; a++) {
        int v = idx[a];
        int b = a - 1;
        while (b >= 0 && in_sizes[idx[b]] < in_sizes[v]) { idx[b + 1] = idx[b]; b--; }
        idx[b + 1] = v;
    }

    const int*   paths      = (const int*)  d_in[idx[0]];
    const int*   edge_ids   = (const int*)  d_in[idx[1]];
    const int*   rand_lens  = (const int*)  d_in[idx[2]];
    const float* centrality = (const float*)d_in[idx[3]];

    const int n_node = in_sizes[idx[0]] / (32 * 8);

    float* out_paths = (float*)d_out;                       // [n_node, 8, 8]
    float* out_edges = out_paths + (long long)n_node * 64;  // [n_node, 8, 7]

    const int threads = 128;                  // 4 warps -> 4 nodes per block
    const int blocks  = (n_node + 3) / 4;
    path_sampling_kernel<<<blocks, threads>>>(paths, edge_ids, rand_lens,
                                              centrality, out_paths, out_edges,
                                              n_node);
}